// round 10
// baseline (speedup 1.0000x reference)
#include <cuda_runtime.h>
#include <cuda_fp16.h>
#include <cstdint>

// ---------------------------------------------------------------------------
// Shapes (fixed by the problem instance)
#define B_   8
#define M_   8192
#define D_   1024
#define MB_  2048
#define POS  32
#define KIN  1056
#define ROWS 16384          // B_*MB_
#define KP   1088           // padded GEMM K: 1024 head + 32 ff + 32 zero

// Scratch (device globals; no allocation allowed)
__device__ __align__(256) __half g_A [(size_t)ROWS * KP];  // ~35.7 MB fp16
__device__ __align__(256) __half g_Ws[(size_t)D_   * KP];  //  ~2.2 MB fp16

// ---------------------------------------------------------------------------
// PTX helpers (baseline sm_80 features only — compute_103-safe)
// ---------------------------------------------------------------------------
__device__ __forceinline__ uint32_t smem_u32(const void* p) {
    uint32_t a;
    asm("{ .reg .u64 t; cvta.to.shared.u64 t, %1; cvt.u32.u64 %0, t; }" : "=r"(a) : "l"(p));
    return a;
}
#define CP16(dst, src) \
    asm volatile("cp.async.cg.shared.global [%0], [%1], 16;" :: "r"(dst), "l"(src) : "memory")
#define CP_COMMIT() asm volatile("cp.async.commit_group;" ::: "memory")
#define CP_WAIT(n)  asm volatile("cp.async.wait_group %0;" :: "n"(n) : "memory")
#define LDSM4(r0, r1, r2, r3, a) \
    asm volatile("ldmatrix.sync.aligned.m8n8.x4.shared.b16 {%0,%1,%2,%3}, [%4];" \
        : "=r"(r0), "=r"(r1), "=r"(r2), "=r"(r3) : "r"(a))
#define MMA16816(d, a, b) \
    asm volatile("mma.sync.aligned.m16n8k16.row.col.f32.f16.f16.f32 " \
        "{%0,%1,%2,%3}, {%4,%5,%6,%7}, {%8,%9}, {%0,%1,%2,%3};" \
        : "+f"((d)[0]), "+f"((d)[1]), "+f"((d)[2]), "+f"((d)[3]) \
        : "r"((a)[0]), "r"((a)[1]), "r"((a)[2]), "r"((a)[3]), "r"((b)[0]), "r"((b)[1]))

#define SWZ(x) ((x) ^ (((x) >> 3) & 0x70))

__device__ __forceinline__ uint32_t pack2(float a, float b) {
    return (uint32_t)__half_as_ushort(__float2half(a)) |
           ((uint32_t)__half_as_ushort(__float2half(b)) << 16);
}

// ---------------------------------------------------------------------------
// Kernel 1: 4-row mean pool -> fp16 head columns (0..1023), row stride KP.
// ---------------------------------------------------------------------------
__global__ __launch_bounds__(256) void pool_kernel(const float4* __restrict__ in) {
    size_t i = (size_t)blockIdx.x * 256 + threadIdx.x;
    int row = (int)(i >> 8);
    int c4  = (int)(i & 255);
    const float4* p = in + ((size_t)row * 4) * 256 + c4;
    float4 a = p[0], b = p[256], d = p[512], e = p[768];
    uint2 v;
    v.x = pack2(0.25f * (a.x + b.x + d.x + e.x), 0.25f * (a.y + b.y + d.y + e.y));
    v.y = pack2(0.25f * (a.z + b.z + d.z + e.z), 0.25f * (a.w + b.w + d.w + e.w));
    *reinterpret_cast<uint2*>(g_A + (size_t)row * KP + c4 * 4) = v;
}

// ---------------------------------------------------------------------------
// Kernel 1b: fill A tail cols 1024..1087 with [ff(mb) | zeros] for all batches.
// ---------------------------------------------------------------------------
__global__ void ff_fill_kernel() {
    int mb = blockIdx.x;
    int j  = threadIdx.x;            // 0..63
    __half h;
    if (j < 32) {
        float pos  = (float)mb / (float)(MB_ - 1);
        int   f    = j & 15;
        float freq = expf((float)f * (6.907755278982137f / 15.0f));
        float ang  = pos * freq;
        h = __float2half((j < 16) ? sinf(ang) : cosf(ang));
    } else {
        h = __float2half(0.0f);      // zero pad cols 1056..1087
    }
    #pragma unroll
    for (int b = 0; b < B_; ++b)
        g_A[(size_t)(b * MB_ + mb) * KP + 1024 + j] = h;
}

// ---------------------------------------------------------------------------
// Kernel 2: W -> fp16, cols 0..1055 from W, 1056..1087 zero.  grid = D_.
// ---------------------------------------------------------------------------
__global__ __launch_bounds__(160) void wsplit_kernel(const float* __restrict__ W) {
    int o = blockIdx.x;
    int t = threadIdx.x;             // 0..159, active t < 136
    if (t >= 136) return;
    uint4 v;
    if (t < 132) {
        const float* src = W + (size_t)o * KIN + t * 8;
        float4 w0 = *reinterpret_cast<const float4*>(src);
        float4 w1 = *reinterpret_cast<const float4*>(src + 4);
        v.x = pack2(w0.x, w0.y);
        v.y = pack2(w0.z, w0.w);
        v.z = pack2(w1.x, w1.y);
        v.w = pack2(w1.z, w1.w);
    } else {
        v.x = v.y = v.z = v.w = 0;
    }
    *reinterpret_cast<uint4*>(g_Ws + (size_t)o * KP + t * 8) = v;
}

// ---------------------------------------------------------------------------
// Kernel 3: fp16 mma.sync GEMM.  C[16384,1024] = A[.,1088] @ Ws[1024,1088]^T + b
// 128x256x64 tiles, 3-stage cp.async, SW128 smem, ldmatrix, 8 warps (2x4),
// warp tile 64x64 (cuts smem re-reads to 128 B/MMA), fp32 accumulators.
// ---------------------------------------------------------------------------
#define BM 128
#define BN 256
#define BK 64
#define NKC 17               // 1088 / 64
#define STAGES 3
#define TILE_A (BM * BK * 2) // 16 KB
#define TILE_W (BN * BK * 2) // 32 KB
#define STG_B  (TILE_A + TILE_W)     // 48 KB per stage
#define SMEM_TOTAL (STAGES * STG_B)  // 144 KB

extern __shared__ char dynsmem[];

__global__ __launch_bounds__(256, 1) void gemm_kernel(float* __restrict__ C,
                                                      const float* __restrict__ bias) {
    const uint32_t sb = smem_u32(dynsmem);
    const int tid  = threadIdx.x;
    const int lane = tid & 31;
    const int wid  = tid >> 5;
    const int wm   = wid >> 2;          // 0..1  (M dir, 64 rows each)
    const int wn   = wid & 3;           // 0..3  (N dir, 64 cols each)
    const int m0 = blockIdx.y * BM;
    const int n0 = blockIdx.x * BN;

    // loaders: 256 threads; A: 1024 16B-chunks (4/thread), B: 2048 (8/thread)
    const int grow = tid >> 3;          // 0..31 base row (stride 32)
    const int gseg = tid & 7;           // 16B segment within 128B row
    const __half* gA = g_A  + (size_t)(m0 + grow) * KP + gseg * 8;
    const __half* gB = g_Ws + (size_t)(n0 + grow) * KP + gseg * 8;

    // hoisted ldmatrix address components: SWZ(row*128+kb) = row*128 + (kb ^ swz)
    uint32_t aBase[4], aSwz[4], bBase[4], bSwz[4];
    #pragma unroll
    for (int mt = 0; mt < 4; ++mt) {
        int r = wm * 64 + mt * 16 + (lane & 15);
        aBase[mt] = (uint32_t)(r * 128);
        aSwz[mt]  = (uint32_t)((r & 7) << 4);
    }
    #pragma unroll
    for (int nt2 = 0; nt2 < 4; ++nt2) {
        int r = wn * 64 + nt2 * 16 + (lane & 15);
        bBase[nt2] = (uint32_t)(r * 128);
        bSwz[nt2]  = (uint32_t)((r & 7) << 4);
    }
    const uint32_t hi16 = (lane >> 4) * 16;

    float acc[4][8][4];                  // [mt][nt][frag] — 128 regs
    #pragma unroll
    for (int i = 0; i < 4; ++i)
        #pragma unroll
        for (int j = 0; j < 8; ++j)
            #pragma unroll
            for (int v = 0; v < 4; ++v) acc[i][j][v] = 0.0f;

    // ---- prologue: prefetch STAGES-1 tiles --------------------------------
    #pragma unroll
    for (int s = 0; s < STAGES - 1; ++s) {
        const uint32_t sa = sb + s * STG_B;
        #pragma unroll
        for (int r = 0; r < 4; ++r) {     // A: 128 rows
            uint32_t off = SWZ((uint32_t)((grow + r * 32) * 128 + gseg * 16));
            CP16(sa + off, gA + (size_t)(r * 32) * KP + s * 64);
        }
        #pragma unroll
        for (int r = 0; r < 8; ++r) {     // B: 256 rows
            uint32_t off = SWZ((uint32_t)((grow + r * 32) * 128 + gseg * 16));
            CP16(sa + TILE_A + off, gB + (size_t)(r * 32) * KP + s * 64);
        }
        CP_COMMIT();
    }

    uint32_t afr[2][4][4], bfr[2][4][4];

    // ---- mainloop ---------------------------------------------------------
    for (int kc = 0; kc < NKC; ++kc) {
        CP_WAIT(1);
        __syncthreads();

        const int kn = kc + STAGES - 1;
        if (kn < NKC) {
            const uint32_t sa = sb + (kn % STAGES) * STG_B;
            #pragma unroll
            for (int r = 0; r < 4; ++r) {
                uint32_t off = SWZ((uint32_t)((grow + r * 32) * 128 + gseg * 16));
                CP16(sa + off, gA + (size_t)(r * 32) * KP + kn * 64);
            }
            #pragma unroll
            for (int r = 0; r < 8; ++r) {
                uint32_t off = SWZ((uint32_t)((grow + r * 32) * 128 + gseg * 16));
                CP16(sa + TILE_A + off, gB + (size_t)(r * 32) * KP + kn * 64);
            }
        }
        CP_COMMIT();

        const uint32_t sA = sb + (kc % STAGES) * STG_B;
        const uint32_t sB = sA + TILE_A;

        // load ks=0 fragments
        {
            const uint32_t kb = hi16;
            #pragma unroll
            for (int mt = 0; mt < 4; ++mt)
                LDSM4(afr[0][mt][0], afr[0][mt][1], afr[0][mt][2], afr[0][mt][3],
                      sA + aBase[mt] + (kb ^ aSwz[mt]));
            #pragma unroll
            for (int nt2 = 0; nt2 < 4; ++nt2)
                LDSM4(bfr[0][nt2][0], bfr[0][nt2][1], bfr[0][nt2][2], bfr[0][nt2][3],
                      sB + bBase[nt2] + (kb ^ bSwz[nt2]));
        }
        #pragma unroll
        for (int ks = 0; ks < 4; ++ks) {
            const int cur = ks & 1, nxt = cur ^ 1;
            if (ks < 3) {
                const uint32_t kb = (ks + 1) * 32 + hi16;
                #pragma unroll
                for (int mt = 0; mt < 4; ++mt)
                    LDSM4(afr[nxt][mt][0], afr[nxt][mt][1], afr[nxt][mt][2], afr[nxt][mt][3],
                          sA + aBase[mt] + (kb ^ aSwz[mt]));
                #pragma unroll
                for (int nt2 = 0; nt2 < 4; ++nt2)
                    LDSM4(bfr[nxt][nt2][0], bfr[nxt][nt2][1], bfr[nxt][nt2][2], bfr[nxt][nt2][3],
                          sB + bBase[nt2] + (kb ^ bSwz[nt2]));
            }
            #pragma unroll
            for (int mt = 0; mt < 4; ++mt) {
                #pragma unroll
                for (int nt = 0; nt < 8; ++nt) {
                    uint32_t bfrag[2] = { bfr[cur][nt >> 1][nt & 1],
                                          bfr[cur][nt >> 1][(nt & 1) + 2] };
                    MMA16816(acc[mt][nt], afr[cur][mt], bfrag);
                }
            }
        }
    }

    // ---- epilogue: + bias[col], write C ------------------------------------
    const int group = lane >> 2;
    const int t4    = lane & 3;
    #pragma unroll
    for (int mt = 0; mt < 4; ++mt) {
        #pragma unroll
        for (int half = 0; half < 2; ++half) {
            const int row = m0 + wm * 64 + mt * 16 + group + half * 8;
            float* cp = C + (size_t)row * D_;
            #pragma unroll
            for (int nt = 0; nt < 8; ++nt) {
                const int col = n0 + wn * 64 + nt * 8 + t4 * 2;
                float2 bv = *reinterpret_cast<const float2*>(bias + col);
                float2 v;
                v.x = acc[mt][nt][half * 2]     + bv.x;
                v.y = acc[mt][nt][half * 2 + 1] + bv.y;
                *reinterpret_cast<float2*>(cp + col) = v;
            }
        }
    }
}

// ---------------------------------------------------------------------------
extern "C" void kernel_launch(void* const* d_in, const int* in_sizes, int n_in,
                              void* d_out, int out_size) {
    const float* beat = (const float*)d_in[0];   // [8, 8192, 1024]
    const float* W    = (const float*)d_in[1];   // [1024, 1056]
    const float* bias = (const float*)d_in[2];   // [1024]
    float* out = (float*)d_out;                  // [8, 2048, 1024]

    cudaFuncSetAttribute(gemm_kernel, cudaFuncAttributeMaxDynamicSharedMemorySize,
                         SMEM_TOTAL);

    pool_kernel<<<ROWS, 256>>>((const float4*)beat);
    ff_fill_kernel<<<MB_, 64>>>();
    wsplit_kernel<<<D_, 160>>>(W);
    dim3 grid(D_ / BN, ROWS / BM);               // (4, 128) = 512 CTAs
    gemm_kernel<<<grid, 256, SMEM_TOTAL>>>(out, bias);
}

// round 11
// speedup vs baseline: 1.5452x; 1.5452x over previous
#include <cuda_runtime.h>
#include <cuda_fp16.h>
#include <cstdint>

// ---------------------------------------------------------------------------
// Shapes (fixed by the problem instance)
#define B_   8
#define M_   8192
#define D_   1024
#define MB_  2048
#define POS  32
#define KIN  1056
#define ROWS 16384          // B_*MB_
#define KP   1088           // padded GEMM K: 1024 head + 32 ff + 32 zero

// Scratch (device globals; no allocation allowed)
__device__ __align__(256) __half g_A [(size_t)ROWS * KP];  // ~35.7 MB fp16
__device__ __align__(256) __half g_Ws[(size_t)D_   * KP];  //  ~2.2 MB fp16

// ---------------------------------------------------------------------------
// PTX helpers (baseline sm_80 features only — compute_103-safe)
// ---------------------------------------------------------------------------
__device__ __forceinline__ uint32_t smem_u32(const void* p) {
    uint32_t a;
    asm("{ .reg .u64 t; cvta.to.shared.u64 t, %1; cvt.u32.u64 %0, t; }" : "=r"(a) : "l"(p));
    return a;
}
#define CP16(dst, src) \
    asm volatile("cp.async.cg.shared.global [%0], [%1], 16;" :: "r"(dst), "l"(src) : "memory")
#define CP_COMMIT() asm volatile("cp.async.commit_group;" ::: "memory")
#define CP_WAIT(n)  asm volatile("cp.async.wait_group %0;" :: "n"(n) : "memory")
#define LDSM4(r0, r1, r2, r3, a) \
    asm volatile("ldmatrix.sync.aligned.m8n8.x4.shared.b16 {%0,%1,%2,%3}, [%4];" \
        : "=r"(r0), "=r"(r1), "=r"(r2), "=r"(r3) : "r"(a))
#define MMA16816(d, a, b) \
    asm volatile("mma.sync.aligned.m16n8k16.row.col.f32.f16.f16.f32 " \
        "{%0,%1,%2,%3}, {%4,%5,%6,%7}, {%8,%9}, {%0,%1,%2,%3};" \
        : "+f"((d)[0]), "+f"((d)[1]), "+f"((d)[2]), "+f"((d)[3]) \
        : "r"((a)[0]), "r"((a)[1]), "r"((a)[2]), "r"((a)[3]), "r"((b)[0]), "r"((b)[1]))

#define SWZ(x) ((x) ^ (((x) >> 3) & 0x70))

__device__ __forceinline__ uint32_t pack2(float a, float b) {
    return (uint32_t)__half_as_ushort(__float2half(a)) |
           ((uint32_t)__half_as_ushort(__float2half(b)) << 16);
}

// ---------------------------------------------------------------------------
// Kernel 1: 4-row mean pool -> fp16 head columns (0..1023), row stride KP.
// ---------------------------------------------------------------------------
__global__ __launch_bounds__(256) void pool_kernel(const float4* __restrict__ in) {
    size_t i = (size_t)blockIdx.x * 256 + threadIdx.x;
    int row = (int)(i >> 8);
    int c4  = (int)(i & 255);
    const float4* p = in + ((size_t)row * 4) * 256 + c4;
    float4 a = p[0], b = p[256], d = p[512], e = p[768];
    uint2 v;
    v.x = pack2(0.25f * (a.x + b.x + d.x + e.x), 0.25f * (a.y + b.y + d.y + e.y));
    v.y = pack2(0.25f * (a.z + b.z + d.z + e.z), 0.25f * (a.w + b.w + d.w + e.w));
    *reinterpret_cast<uint2*>(g_A + (size_t)row * KP + c4 * 4) = v;
}

// ---------------------------------------------------------------------------
// Kernel 1b: fill A tail cols 1024..1087 with [ff(mb) | zeros] for all batches.
// ---------------------------------------------------------------------------
__global__ void ff_fill_kernel() {
    int mb = blockIdx.x;
    int j  = threadIdx.x;            // 0..63
    __half h;
    if (j < 32) {
        float pos  = (float)mb / (float)(MB_ - 1);
        int   f    = j & 15;
        float freq = expf((float)f * (6.907755278982137f / 15.0f));
        float ang  = pos * freq;
        h = __float2half((j < 16) ? sinf(ang) : cosf(ang));
    } else {
        h = __float2half(0.0f);      // zero pad cols 1056..1087
    }
    #pragma unroll
    for (int b = 0; b < B_; ++b)
        g_A[(size_t)(b * MB_ + mb) * KP + 1024 + j] = h;
}

// ---------------------------------------------------------------------------
// Kernel 2: W -> fp16, cols 0..1055 from W, 1056..1087 zero.  grid = D_.
// ---------------------------------------------------------------------------
__global__ __launch_bounds__(160) void wsplit_kernel(const float* __restrict__ W) {
    int o = blockIdx.x;
    int t = threadIdx.x;             // 0..159, active t < 136
    if (t >= 136) return;
    uint4 v;
    if (t < 132) {
        const float* src = W + (size_t)o * KIN + t * 8;
        float4 w0 = *reinterpret_cast<const float4*>(src);
        float4 w1 = *reinterpret_cast<const float4*>(src + 4);
        v.x = pack2(w0.x, w0.y);
        v.y = pack2(w0.z, w0.w);
        v.z = pack2(w1.x, w1.y);
        v.w = pack2(w1.z, w1.w);
    } else {
        v.x = v.y = v.z = v.w = 0;
    }
    *reinterpret_cast<uint4*>(g_Ws + (size_t)o * KP + t * 8) = v;
}

// ---------------------------------------------------------------------------
// Kernel 3: fp16 mma.sync GEMM.  C[16384,1024] = A[.,1088] @ Ws[1024,1088]^T + b
// 128x128x64 tiles, SMALL CTA: 128 threads, 4 warps (2x2), warp tile 64x64.
// 3-stage cp.async (96 KB) -> 2 independent CTAs per SM (barrier desync).
// ---------------------------------------------------------------------------
#define BM 128
#define BN 128
#define BK 64
#define NKC 17               // 1088 / 64
#define STAGES 3
#define TILE_A (BM * BK * 2) // 16 KB
#define TILE_W (BN * BK * 2) // 16 KB
#define STG_B  (TILE_A + TILE_W)     // 32 KB per stage
#define SMEM_TOTAL (STAGES * STG_B)  // 96 KB

extern __shared__ char dynsmem[];

__global__ __launch_bounds__(128, 2) void gemm_kernel(float* __restrict__ C,
                                                      const float* __restrict__ bias) {
    const uint32_t sb = smem_u32(dynsmem);
    const int tid  = threadIdx.x;
    const int lane = tid & 31;
    const int wid  = tid >> 5;          // 0..3
    const int wm   = wid >> 1;          // 0..1  (M dir, 64 rows each)
    const int wn   = wid & 1;           // 0..1  (N dir, 64 cols each)
    const int m0 = blockIdx.y * BM;
    const int n0 = blockIdx.x * BN;

    // loaders: 128 threads; A: 1024 16B-chunks (8/thread), B: 1024 (8/thread)
    const int grow = tid >> 3;          // 0..15 base row (stride 16)
    const int gseg = tid & 7;           // 16B segment within 128B row
    const __half* gA = g_A  + (size_t)(m0 + grow) * KP + gseg * 8;
    const __half* gB = g_Ws + (size_t)(n0 + grow) * KP + gseg * 8;

    // hoisted ldmatrix address components: SWZ(row*128+kb) = row*128 + (kb ^ swz)
    uint32_t aBase[4], aSwz[4], bBase[4], bSwz[4];
    #pragma unroll
    for (int mt = 0; mt < 4; ++mt) {
        int r = wm * 64 + mt * 16 + (lane & 15);
        aBase[mt] = (uint32_t)(r * 128);
        aSwz[mt]  = (uint32_t)((r & 7) << 4);
    }
    #pragma unroll
    for (int nt2 = 0; nt2 < 4; ++nt2) {
        int r = wn * 64 + nt2 * 16 + (lane & 15);
        bBase[nt2] = (uint32_t)(r * 128);
        bSwz[nt2]  = (uint32_t)((r & 7) << 4);
    }
    const uint32_t hi16 = (lane >> 4) * 16;

    float acc[4][8][4];                  // 128 regs
    #pragma unroll
    for (int i = 0; i < 4; ++i)
        #pragma unroll
        for (int j = 0; j < 8; ++j)
            #pragma unroll
            for (int v = 0; v < 4; ++v) acc[i][j][v] = 0.0f;

    // ---- prologue: prefetch STAGES-1 tiles --------------------------------
    #pragma unroll
    for (int s = 0; s < STAGES - 1; ++s) {
        const uint32_t sa = sb + s * STG_B;
        #pragma unroll
        for (int r = 0; r < 8; ++r) {     // A: 128 rows (16 per iter)
            uint32_t off = SWZ((uint32_t)((grow + r * 16) * 128 + gseg * 16));
            CP16(sa + off, gA + (size_t)(r * 16) * KP + s * 64);
        }
        #pragma unroll
        for (int r = 0; r < 8; ++r) {     // B: 128 rows
            uint32_t off = SWZ((uint32_t)((grow + r * 16) * 128 + gseg * 16));
            CP16(sa + TILE_A + off, gB + (size_t)(r * 16) * KP + s * 64);
        }
        CP_COMMIT();
    }

    uint32_t afr[2][4][4], bfr[2][4][4];

    // ---- mainloop ---------------------------------------------------------
    for (int kc = 0; kc < NKC; ++kc) {
        CP_WAIT(1);
        __syncthreads();

        const int kn = kc + STAGES - 1;
        if (kn < NKC) {
            const uint32_t sa = sb + (kn % STAGES) * STG_B;
            #pragma unroll
            for (int r = 0; r < 8; ++r) {
                uint32_t off = SWZ((uint32_t)((grow + r * 16) * 128 + gseg * 16));
                CP16(sa + off, gA + (size_t)(r * 16) * KP + kn * 64);
            }
            #pragma unroll
            for (int r = 0; r < 8; ++r) {
                uint32_t off = SWZ((uint32_t)((grow + r * 16) * 128 + gseg * 16));
                CP16(sa + TILE_A + off, gB + (size_t)(r * 16) * KP + kn * 64);
            }
        }
        CP_COMMIT();

        const uint32_t sA = sb + (kc % STAGES) * STG_B;
        const uint32_t sB = sA + TILE_A;

        // load ks=0 fragments
        {
            const uint32_t kb = hi16;
            #pragma unroll
            for (int mt = 0; mt < 4; ++mt)
                LDSM4(afr[0][mt][0], afr[0][mt][1], afr[0][mt][2], afr[0][mt][3],
                      sA + aBase[mt] + (kb ^ aSwz[mt]));
            #pragma unroll
            for (int nt2 = 0; nt2 < 4; ++nt2)
                LDSM4(bfr[0][nt2][0], bfr[0][nt2][1], bfr[0][nt2][2], bfr[0][nt2][3],
                      sB + bBase[nt2] + (kb ^ bSwz[nt2]));
        }
        #pragma unroll
        for (int ks = 0; ks < 4; ++ks) {
            const int cur = ks & 1, nxt = cur ^ 1;
            if (ks < 3) {
                const uint32_t kb = (ks + 1) * 32 + hi16;
                #pragma unroll
                for (int mt = 0; mt < 4; ++mt)
                    LDSM4(afr[nxt][mt][0], afr[nxt][mt][1], afr[nxt][mt][2], afr[nxt][mt][3],
                          sA + aBase[mt] + (kb ^ aSwz[mt]));
                #pragma unroll
                for (int nt2 = 0; nt2 < 4; ++nt2)
                    LDSM4(bfr[nxt][nt2][0], bfr[nxt][nt2][1], bfr[nxt][nt2][2], bfr[nxt][nt2][3],
                          sB + bBase[nt2] + (kb ^ bSwz[nt2]));
            }
            #pragma unroll
            for (int mt = 0; mt < 4; ++mt) {
                #pragma unroll
                for (int nt = 0; nt < 8; ++nt) {
                    uint32_t bfrag[2] = { bfr[cur][nt >> 1][nt & 1],
                                          bfr[cur][nt >> 1][(nt & 1) + 2] };
                    MMA16816(acc[mt][nt], afr[cur][mt], bfrag);
                }
            }
        }
    }

    // ---- epilogue: + bias[col], write C ------------------------------------
    const int group = lane >> 2;
    const int t4    = lane & 3;
    #pragma unroll
    for (int mt = 0; mt < 4; ++mt) {
        #pragma unroll
        for (int half = 0; half < 2; ++half) {
            const int row = m0 + wm * 64 + mt * 16 + group + half * 8;
            float* cp = C + (size_t)row * D_;
            #pragma unroll
            for (int nt = 0; nt < 8; ++nt) {
                const int col = n0 + wn * 64 + nt * 8 + t4 * 2;
                float2 bv = *reinterpret_cast<const float2*>(bias + col);
                float2 v;
                v.x = acc[mt][nt][half * 2]     + bv.x;
                v.y = acc[mt][nt][half * 2 + 1] + bv.y;
                *reinterpret_cast<float2*>(cp + col) = v;
            }
        }
    }
}

// ---------------------------------------------------------------------------
extern "C" void kernel_launch(void* const* d_in, const int* in_sizes, int n_in,
                              void* d_out, int out_size) {
    const float* beat = (const float*)d_in[0];   // [8, 8192, 1024]
    const float* W    = (const float*)d_in[1];   // [1024, 1056]
    const float* bias = (const float*)d_in[2];   // [1024]
    float* out = (float*)d_out;                  // [8, 2048, 1024]

    cudaFuncSetAttribute(gemm_kernel, cudaFuncAttributeMaxDynamicSharedMemorySize,
                         SMEM_TOTAL);

    pool_kernel<<<ROWS, 256>>>((const float4*)beat);
    ff_fill_kernel<<<MB_, 64>>>();
    wsplit_kernel<<<D_, 160>>>(W);
    dim3 grid(D_ / BN, ROWS / BM);               // (8, 128) = 1024 CTAs
    gemm_kernel<<<grid, 128, SMEM_TOTAL>>>(out, bias);
}